// round 10
// baseline (speedup 1.0000x reference)
#include <cuda_runtime.h>
#include <cstdint>

#define N_NODES   100000
#define N_EDGES   1600000
#define N_ETYPES  3
#define IN_FEATS  128
#define HEADS     4
#define OUT_FEATS 16
#define HD        64
#define NEG_SLOPE 0.2f
#define SCAN_B    1024
#define NB        ((N_NODES + SCAN_B - 1) / SCAN_B)   // 98

// ---------------- device scratch (static globals; no allocation) -------------
__device__ float4 g_feat[N_NODES * 16];   // [N][64] as 16 x float4 (25.6 MB)
__device__ float4 g_el[N_NODES];          // [N][4]
__device__ float4 g_er[N_NODES];          // [N][4]
__device__ float4 g_ee[N_ETYPES];         // [3][4]
__device__ int    g_cnt[N_NODES];
__device__ int    g_incl[N_NODES];
__device__ int    g_bsum[NB];
__device__ int    g_boff[NB];
__device__ int    g_rowptr[N_NODES + 1];
__device__ int    g_cur[N_NODES];
__device__ int2   g_es[N_EDGES];          // sorted: {src, orig_id*4 | etype}

__device__ __forceinline__ uint32_t to_tf32(float f) {
    uint32_t r;
    asm("cvt.rna.tf32.f32 %0, %1;" : "=r"(r) : "f"(f));
    return r;
}

__device__ __forceinline__ void mma_tf32(float* c, const uint32_t* a, const uint32_t* b) {
    asm("mma.sync.aligned.m16n8k8.row.col.f32.tf32.tf32.f32 "
        "{%0,%1,%2,%3}, {%4,%5,%6,%7}, {%8,%9}, {%0,%1,%2,%3};"
        : "+f"(c[0]), "+f"(c[1]), "+f"(c[2]), "+f"(c[3])
        : "r"(a[0]), "r"(a[1]), "r"(a[2]), "r"(a[3]), "r"(b[0]), "r"(b[1]));
}

__device__ __forceinline__ void cp_async16(void* dst, const void* src, bool valid) {
    uint32_t d = (uint32_t)__cvta_generic_to_shared(dst);
    int sz = valid ? 16 : 0;
    asm volatile("cp.async.cg.shared.global [%0], [%1], 16, %2;"
                 :: "r"(d), "l"(src), "r"(sz));
}

// ---------------- init: zero histogram ---------------------------------------
__global__ void k_init() {
    int i = blockIdx.x * 256 + threadIdx.x;
    if (i < N_NODES) g_cnt[i] = 0;
}

// ---------------- per-etype edge term ee[t][h] -------------------------------
__global__ void k_ee(const float* __restrict__ W_e, const float* __restrict__ attn_e,
                     const float* __restrict__ edge_emb) {
    int w = threadIdx.x >> 5, lane = threadIdx.x & 31;
    if (w >= N_ETYPES * HEADS) return;
    int t = w >> 2, h = w & 3;
    float acc = 0.0f;
#pragma unroll
    for (int ei = 0; ei < 2; ei++) {
        int e = lane + ei * 32;
        float dot = 0.0f;
#pragma unroll 8
        for (int k = 0; k < 64; k++)
            dot += edge_emb[t * 64 + k] * W_e[k * 256 + h * 64 + e];
        acc += dot * attn_e[h * 64 + e];
    }
#pragma unroll
    for (int o = 16; o; o >>= 1) acc += __shfl_xor_sync(0xffffffffu, acc, o);
    if (lane == 0) ((float*)g_ee)[t * 4 + h] = acc;
}

// ---------------- counting sort: histogram ------------------------------------
__global__ __launch_bounds__(256) void k_hist(const int* __restrict__ dst) {
    int i = blockIdx.x * 256 + threadIdx.x;
    if (i < N_EDGES) atomicAdd(&g_cnt[dst[i]], 1);
}

// ---------------- GEMM: feat = x @ W via tf32 HMMA, cp.async 2-stage ---------
#define AS_STRIDE 40
#define BS_STRIDE 72
#define AS_WORDS  (128 * AS_STRIDE)
#define BS_WORDS  (32 * BS_STRIDE)
#define GEMM_SMEM ((2 * (AS_WORDS + BS_WORDS)) * 4)

__global__ __launch_bounds__(256) void k_gemm(const float* __restrict__ x,
                                              const float* __restrict__ W,
                                              const float* __restrict__ attn_l,
                                              const float* __restrict__ attn_r) {
    extern __shared__ float smem[];
    float* AsF = smem;
    float* BsF = smem + 2 * AS_WORDS;

    int tid  = threadIdx.x;
    int lane = tid & 31, wid = tid >> 5;
    int warp_m = wid & 3, warp_n = wid >> 2;
    int g = lane >> 2, t = lane & 3;
    int rbase = warp_m * 32, cbase = warp_n * 32;
    int rb = blockIdx.x * 128;

    float acc[2][4][4] = {};

    auto stage = [&](int kt, int b) {
#pragma unroll
        for (int i = 0; i < 4; i++) {
            int s4 = tid + 256 * i;
            int row = s4 >> 3, kq = s4 & 7;
            int gr = rb + row;
            int kp = kq ^ ((row >> 2) & 1);
            cp_async16(&AsF[b * AS_WORDS + row * AS_STRIDE + kp * 4],
                       &x[(long)gr * IN_FEATS + kt * 32 + kq * 4], gr < N_NODES);
        }
#pragma unroll
        for (int i = 0; i < 2; i++) {
            int s4 = tid + 256 * i;
            int k = s4 >> 4, c4 = s4 & 15;
            cp_async16(&BsF[b * BS_WORDS + k * BS_STRIDE + c4 * 4],
                       &W[(long)(kt * 32 + k) * HD + c4 * 4], true);
        }
        asm volatile("cp.async.commit_group;");
    };

    stage(0, 0);
    int s = 0;

#pragma unroll
    for (int kt = 0; kt < 4; kt++) {
        if (kt < 3) stage(kt + 1, s ^ 1);
        if (kt < 3) asm volatile("cp.async.wait_group 1;");
        else        asm volatile("cp.async.wait_group 0;");
        __syncthreads();

        const float* Ac = &AsF[s * AS_WORDS];
        const float* Bc = &BsF[s * BS_WORDS];
#pragma unroll
        for (int ks = 0; ks < 4; ks++) {
            int kk = ks * 8;
            uint32_t a[2][4];
#pragma unroll
            for (int mt = 0; mt < 2; mt++) {
                int r0 = rbase + mt * 16 + g;
                int c0 = kk + t, c1 = kk + t + 4;
                int p0 = ((c0 >> 2) ^ ((r0 >> 2) & 1)) * 4 + (c0 & 3);
                int p0b = ((c0 >> 2) ^ (((r0 + 8) >> 2) & 1)) * 4 + (c0 & 3);
                int p1 = ((c1 >> 2) ^ ((r0 >> 2) & 1)) * 4 + (c1 & 3);
                int p1b = ((c1 >> 2) ^ (((r0 + 8) >> 2) & 1)) * 4 + (c1 & 3);
                a[mt][0] = to_tf32(Ac[r0 * AS_STRIDE + p0]);
                a[mt][1] = to_tf32(Ac[(r0 + 8) * AS_STRIDE + p0b]);
                a[mt][2] = to_tf32(Ac[r0 * AS_STRIDE + p1]);
                a[mt][3] = to_tf32(Ac[(r0 + 8) * AS_STRIDE + p1b]);
            }
            uint32_t b[4][2];
#pragma unroll
            for (int nt = 0; nt < 4; nt++) {
                int n = cbase + nt * 8 + g;
                b[nt][0] = to_tf32(Bc[(kk + t) * BS_STRIDE + n]);
                b[nt][1] = to_tf32(Bc[(kk + t + 4) * BS_STRIDE + n]);
            }
#pragma unroll
            for (int mt = 0; mt < 2; mt++)
#pragma unroll
                for (int nt = 0; nt < 4; nt++)
                    mma_tf32(acc[mt][nt], a[mt], b[nt]);
        }
        __syncthreads();
        s ^= 1;
    }

    int hA = warp_n * 2, hB = hA + 1;
    float2 alA[2], arA[2], alB[2], arB[2];
#pragma unroll
    for (int q = 0; q < 2; q++) {
        alA[q] = *(const float2*)&attn_l[hA * 16 + q * 8 + t * 2];
        arA[q] = *(const float2*)&attn_r[hA * 16 + q * 8 + t * 2];
        alB[q] = *(const float2*)&attn_l[hB * 16 + q * 8 + t * 2];
        arB[q] = *(const float2*)&attn_r[hB * 16 + q * 8 + t * 2];
    }
    float* gfeat = (float*)g_feat;
#pragma unroll
    for (int mt = 0; mt < 2; mt++)
#pragma unroll
    for (int rr = 0; rr < 2; rr++) {
        int r = rb + rbase + mt * 16 + g + rr * 8;
        float v[4][2];
#pragma unroll
        for (int nt = 0; nt < 4; nt++) {
            v[nt][0] = acc[mt][nt][rr * 2];
            v[nt][1] = acc[mt][nt][rr * 2 + 1];
        }
        if (r < N_NODES) {
#pragma unroll
            for (int nt = 0; nt < 4; nt++)
                *(float2*)&gfeat[(long)r * HD + cbase + nt * 8 + t * 2] =
                    make_float2(v[nt][0], v[nt][1]);
        }
        float elA = v[0][0] * alA[0].x + v[0][1] * alA[0].y + v[1][0] * alA[1].x + v[1][1] * alA[1].y;
        float erA = v[0][0] * arA[0].x + v[0][1] * arA[0].y + v[1][0] * arA[1].x + v[1][1] * arA[1].y;
        float elB = v[2][0] * alB[0].x + v[2][1] * alB[0].y + v[3][0] * alB[1].x + v[3][1] * alB[1].y;
        float erB = v[2][0] * arB[0].x + v[2][1] * arB[0].y + v[3][0] * arB[1].x + v[3][1] * arB[1].y;
#pragma unroll
        for (int o = 1; o <= 2; o <<= 1) {
            elA += __shfl_xor_sync(0xffffffffu, elA, o);
            erA += __shfl_xor_sync(0xffffffffu, erA, o);
            elB += __shfl_xor_sync(0xffffffffu, elB, o);
            erB += __shfl_xor_sync(0xffffffffu, erB, o);
        }
        if (t == 0 && r < N_NODES) {
            ((float*)g_el)[r * 4 + hA] = elA;
            ((float*)g_el)[r * 4 + hB] = elB;
            ((float*)g_er)[r * 4 + hA] = erA;
            ((float*)g_er)[r * 4 + hB] = erB;
        }
    }
}

// ---------------- counting sort: scan + scatter -------------------------------
__global__ __launch_bounds__(SCAN_B) void k_scan1() {
    __shared__ int sh[SCAN_B];
    int b = blockIdx.x, t = threadIdx.x;
    int i = b * SCAN_B + t;
    sh[t] = (i < N_NODES) ? g_cnt[i] : 0;
#pragma unroll
    for (int o = 1; o < SCAN_B; o <<= 1) {
        __syncthreads();
        int add = (t >= o) ? sh[t - o] : 0;
        __syncthreads();
        sh[t] += add;
    }
    __syncthreads();
    if (i < N_NODES) g_incl[i] = sh[t];
    if (t == SCAN_B - 1) g_bsum[b] = sh[t];
}

__global__ void k_scan2() {
    __shared__ int sh[128];
    int t = threadIdx.x;
    int v = (t < NB) ? g_bsum[t] : 0;
    sh[t] = v;
#pragma unroll
    for (int o = 1; o < 128; o <<= 1) {
        __syncthreads();
        int add = (t >= o) ? sh[t - o] : 0;
        __syncthreads();
        sh[t] += add;
    }
    __syncthreads();
    if (t < NB) g_boff[t] = sh[t] - v;
}

__global__ void k_scan3() {
    int i = blockIdx.x * 256 + threadIdx.x;
    if (i < N_NODES) {
        int s = g_boff[i >> 10] + g_incl[i] - g_cnt[i];
        g_rowptr[i] = s;
        g_cur[i] = s;
    }
    if (i == 0) g_rowptr[N_NODES] = N_EDGES;
}

__global__ __launch_bounds__(256) void k_scatter(const int* __restrict__ src,
                                                 const int* __restrict__ dst,
                                                 const int* __restrict__ et) {
    int i = blockIdx.x * 256 + threadIdx.x;
    if (i >= N_EDGES) return;
    int p = atomicAdd(&g_cur[dst[i]], 1);
    g_es[p] = make_int2(src[i], (i << 2) | et[i]);
}

// ---------------- fused softmax + aggregate: one warp per dst node -----------
// Phase A: lane-per-edge score/exp (MLP=32), ev+src parked in smem.
// Phase B: half-warp-per-edge feat accumulation, ev from smem, unroll x2.
// a written once: normalized from registers (deg<=32) or unnorm + in-warp fixup.
__global__ __launch_bounds__(256) void k_agg(float* __restrict__ rst,
                                             float4* __restrict__ out_a4) {
    __shared__ float4 s_ev[8][32];
    __shared__ int    s_src[8][32];
    int wv   = threadIdx.x >> 5;
    int lane = threadIdx.x & 31;
    int d = (blockIdx.x * 256 + threadIdx.x) >> 5;
    if (d >= N_NODES) return;
    int start = g_rowptr[d], end = g_rowptr[d + 1];
    int deg = end - start;
    int sl = lane & 15, half = lane >> 4;
    float4* rout4 = (float4*)(rst + (long)d * HD);
    if (deg == 0) {
        if (half == 0) rout4[sl] = make_float4(0.f, 0.f, 0.f, 0.f);
        return;
    }

    float4 er4 = g_er[d];
    float4 ee0 = g_ee[0], ee1 = g_ee[1], ee2 = g_ee[2];

    int h = sl >> 2;                       // head of float4-col sl (phase B)
    float4 zac = make_float4(0.f, 0.f, 0.f, 0.f);
    float4 fac = make_float4(0.f, 0.f, 0.f, 0.f);
    int nch = (deg + 31) >> 5;
    float4 myev = make_float4(0.f, 0.f, 0.f, 0.f);
    int myorig = -1;

    for (int c = 0; c < nch; c++) {
        int e = start + c * 32 + lane;
        bool val = e < end;
        // ---- phase A: lane-per-edge scores
        int2 m = val ? g_es[e] : make_int2(0, 0);
        float4 ev = make_float4(0.f, 0.f, 0.f, 0.f);
        if (val) {
            float4 el = g_el[m.x];
            int t = m.y & 3;
            float4 ee = (t == 0) ? ee0 : ((t == 1) ? ee1 : ee2);
            float4 sc;
            sc.x = el.x + er4.x + ee.x;
            sc.y = el.y + er4.y + ee.y;
            sc.z = el.z + er4.z + ee.z;
            sc.w = el.w + er4.w + ee.w;
            sc.x = sc.x > 0.f ? sc.x : NEG_SLOPE * sc.x;
            sc.y = sc.y > 0.f ? sc.y : NEG_SLOPE * sc.y;
            sc.z = sc.z > 0.f ? sc.z : NEG_SLOPE * sc.z;
            sc.w = sc.w > 0.f ? sc.w : NEG_SLOPE * sc.w;
            ev.x = __expf(sc.x); ev.y = __expf(sc.y);
            ev.z = __expf(sc.z); ev.w = __expf(sc.w);
        }
        zac.x += ev.x; zac.y += ev.y; zac.z += ev.z; zac.w += ev.w;
        s_ev[wv][lane] = ev;
        s_src[wv][lane] = m.x;
        if (nch == 1) { myev = ev; myorig = val ? (m.y >> 2) : -1; }
        else if (val) __stcs(&out_a4[m.y >> 2], ev);       // unnormalized, fixed later
        __syncwarp();

        // ---- phase B: half-warp per edge, 2 edges per half in flight
        int cnt = min(32, end - (start + c * 32));
        const float* evp = (const float*)&s_ev[wv][0];
        for (int p0 = 0; p0 < cnt; p0 += 4) {
            int ea = p0 + half, eb = p0 + 2 + half;
            if (ea < cnt) {
                int sa = s_src[wv][ea];
                float evh = evp[ea * 4 + h];
                float4 f = g_feat[(long)sa * 16 + sl];
                fac.x += f.x * evh; fac.y += f.y * evh;
                fac.z += f.z * evh; fac.w += f.w * evh;
            }
            if (eb < cnt) {
                int sb = s_src[wv][eb];
                float evh = evp[eb * 4 + h];
                float4 f = g_feat[(long)sb * 16 + sl];
                fac.x += f.x * evh; fac.y += f.y * evh;
                fac.z += f.z * evh; fac.w += f.w * evh;
            }
        }
        __syncwarp();
    }

    // ---- z reduce across warp (all heads)
#pragma unroll
    for (int o = 16; o; o >>= 1) {
        zac.x += __shfl_xor_sync(0xffffffffu, zac.x, o);
        zac.y += __shfl_xor_sync(0xffffffffu, zac.y, o);
        zac.z += __shfl_xor_sync(0xffffffffu, zac.z, o);
        zac.w += __shfl_xor_sync(0xffffffffu, zac.w, o);
    }
    float4 invz = make_float4(1.f / zac.x, 1.f / zac.y, 1.f / zac.z, 1.f / zac.w);
    float izh = ((const float*)&invz)[h];

    // ---- combine halves, write rst
    fac.x += __shfl_xor_sync(0xffffffffu, fac.x, 16);
    fac.y += __shfl_xor_sync(0xffffffffu, fac.y, 16);
    fac.z += __shfl_xor_sync(0xffffffffu, fac.z, 16);
    fac.w += __shfl_xor_sync(0xffffffffu, fac.w, 16);
    if (half == 0)
        rout4[sl] = make_float4(fac.x * izh, fac.y * izh, fac.z * izh, fac.w * izh);

    // ---- write / fix a
    if (nch == 1) {
        if (myorig >= 0) {
            float4 a = make_float4(myev.x * invz.x, myev.y * invz.y,
                                   myev.z * invz.z, myev.w * invz.w);
            __stcs(&out_a4[myorig], a);
        }
    } else {
        for (int e = start + lane; e < end; e += 32) {
            int2 m = g_es[e];
            float4 a = out_a4[m.y >> 2];
            a.x *= invz.x; a.y *= invz.y; a.z *= invz.z; a.w *= invz.w;
            __stcs(&out_a4[m.y >> 2], a);
        }
    }
}

// ---------------- launch ------------------------------------------------------
extern "C" void kernel_launch(void* const* d_in, const int* in_sizes, int n_in,
                              void* d_out, int out_size) {
    const float* x        = (const float*)d_in[0];
    const float* W        = (const float*)d_in[1];
    const float* W_e      = (const float*)d_in[2];
    const float* attn_l   = (const float*)d_in[3];
    const float* attn_r   = (const float*)d_in[4];
    const float* attn_e   = (const float*)d_in[5];
    const float* edge_emb = (const float*)d_in[6];
    const int*   src      = (const int*)d_in[7];
    const int*   dst      = (const int*)d_in[8];
    const int*   et       = (const int*)d_in[9];

    float* rst   = (float*)d_out;
    float* out_a = rst + (long)N_NODES * HD;

    int nb = (N_NODES + 255) / 256;
    int eb = (N_EDGES + 255) / 256;

    cudaFuncSetAttribute(k_gemm, cudaFuncAttributeMaxDynamicSharedMemorySize, GEMM_SMEM);

    k_init<<<nb, 256>>>();
    k_ee<<<1, 384>>>(W_e, attn_e, edge_emb);
    k_hist<<<eb, 256>>>(dst);
    k_gemm<<<(N_NODES + 127) / 128, 256, GEMM_SMEM>>>(x, W, attn_l, attn_r);   // 4th: profiled
    k_scan1<<<NB, SCAN_B>>>();
    k_scan2<<<1, 128>>>();
    k_scan3<<<nb, 256>>>();
    k_scatter<<<eb, 256>>>(src, dst, et);
    k_agg<<<(N_NODES * 32 + 255) / 256, 256>>>(rst, (float4*)out_a);
}

// round 11
// speedup vs baseline: 1.0401x; 1.0401x over previous
#include <cuda_runtime.h>
#include <cuda_fp16.h>
#include <cstdint>

#define N_NODES   100000
#define N_EDGES   1600000
#define N_ETYPES  3
#define IN_FEATS  128
#define HEADS     4
#define OUT_FEATS 16
#define HD        64
#define NEG_SLOPE 0.2f
#define SCAN_B    1024
#define NB        ((N_NODES + SCAN_B - 1) / SCAN_B)   // 98

// ---------------- device scratch (static globals; no allocation) -------------
__device__ __half g_feat[N_NODES * HD];   // [N][64] fp16 (12.8 MB)
__device__ float4 g_el[N_NODES];          // [N][4]
__device__ float4 g_er[N_NODES];          // [N][4]
__device__ float4 g_ee[N_ETYPES];         // [3][4]
__device__ int    g_cnt[N_NODES];
__device__ int    g_incl[N_NODES];
__device__ int    g_bsum[NB];
__device__ int    g_boff[NB];
__device__ int    g_rowptr[N_NODES + 1];
__device__ int    g_cur[N_NODES];
__device__ int2   g_es[N_EDGES];          // sorted: {src, orig_id*4 | etype}

__device__ __forceinline__ uint32_t to_tf32(float f) {
    uint32_t r;
    asm("cvt.rna.tf32.f32 %0, %1;" : "=r"(r) : "f"(f));
    return r;
}

__device__ __forceinline__ void mma_tf32(float* c, const uint32_t* a, const uint32_t* b) {
    asm("mma.sync.aligned.m16n8k8.row.col.f32.tf32.tf32.f32 "
        "{%0,%1,%2,%3}, {%4,%5,%6,%7}, {%8,%9}, {%0,%1,%2,%3};"
        : "+f"(c[0]), "+f"(c[1]), "+f"(c[2]), "+f"(c[3])
        : "r"(a[0]), "r"(a[1]), "r"(a[2]), "r"(a[3]), "r"(b[0]), "r"(b[1]));
}

__device__ __forceinline__ void cp_async16(void* dst, const void* src, bool valid) {
    uint32_t d = (uint32_t)__cvta_generic_to_shared(dst);
    int sz = valid ? 16 : 0;
    asm volatile("cp.async.cg.shared.global [%0], [%1], 16, %2;"
                 :: "r"(d), "l"(src), "r"(sz));
}

// ---------------- init: zero histogram ---------------------------------------
__global__ void k_init() {
    int i = blockIdx.x * 256 + threadIdx.x;
    if (i < N_NODES) g_cnt[i] = 0;
}

// ---------------- per-etype edge term ee[t][h] -------------------------------
__global__ void k_ee(const float* __restrict__ W_e, const float* __restrict__ attn_e,
                     const float* __restrict__ edge_emb) {
    int w = threadIdx.x >> 5, lane = threadIdx.x & 31;
    if (w >= N_ETYPES * HEADS) return;
    int t = w >> 2, h = w & 3;
    float acc = 0.0f;
#pragma unroll
    for (int ei = 0; ei < 2; ei++) {
        int e = lane + ei * 32;
        float dot = 0.0f;
#pragma unroll 8
        for (int k = 0; k < 64; k++)
            dot += edge_emb[t * 64 + k] * W_e[k * 256 + h * 64 + e];
        acc += dot * attn_e[h * 64 + e];
    }
#pragma unroll
    for (int o = 16; o; o >>= 1) acc += __shfl_xor_sync(0xffffffffu, acc, o);
    if (lane == 0) ((float*)g_ee)[t * 4 + h] = acc;
}

// ---------------- counting sort: histogram ------------------------------------
__global__ __launch_bounds__(256) void k_hist(const int* __restrict__ dst) {
    int i = blockIdx.x * 256 + threadIdx.x;
    if (i < N_EDGES) atomicAdd(&g_cnt[dst[i]], 1);
}

// ---------------- GEMM: feat = x @ W via tf32 HMMA, cp.async 2-stage ---------
#define AS_STRIDE 40
#define BS_STRIDE 72
#define AS_WORDS  (128 * AS_STRIDE)
#define BS_WORDS  (32 * BS_STRIDE)
#define GEMM_SMEM ((2 * (AS_WORDS + BS_WORDS)) * 4)

__global__ __launch_bounds__(256) void k_gemm(const float* __restrict__ x,
                                              const float* __restrict__ W,
                                              const float* __restrict__ attn_l,
                                              const float* __restrict__ attn_r) {
    extern __shared__ float smem[];
    float* AsF = smem;
    float* BsF = smem + 2 * AS_WORDS;

    int tid  = threadIdx.x;
    int lane = tid & 31, wid = tid >> 5;
    int warp_m = wid & 3, warp_n = wid >> 2;
    int g = lane >> 2, t = lane & 3;
    int rbase = warp_m * 32, cbase = warp_n * 32;
    int rb = blockIdx.x * 128;

    float acc[2][4][4] = {};

    auto stage = [&](int kt, int b) {
#pragma unroll
        for (int i = 0; i < 4; i++) {
            int s4 = tid + 256 * i;
            int row = s4 >> 3, kq = s4 & 7;
            int gr = rb + row;
            int kp = kq ^ ((row >> 2) & 1);
            cp_async16(&AsF[b * AS_WORDS + row * AS_STRIDE + kp * 4],
                       &x[(long)gr * IN_FEATS + kt * 32 + kq * 4], gr < N_NODES);
        }
#pragma unroll
        for (int i = 0; i < 2; i++) {
            int s4 = tid + 256 * i;
            int k = s4 >> 4, c4 = s4 & 15;
            cp_async16(&BsF[b * BS_WORDS + k * BS_STRIDE + c4 * 4],
                       &W[(long)(kt * 32 + k) * HD + c4 * 4], true);
        }
        asm volatile("cp.async.commit_group;");
    };

    stage(0, 0);
    int s = 0;

#pragma unroll
    for (int kt = 0; kt < 4; kt++) {
        if (kt < 3) stage(kt + 1, s ^ 1);
        if (kt < 3) asm volatile("cp.async.wait_group 1;");
        else        asm volatile("cp.async.wait_group 0;");
        __syncthreads();

        const float* Ac = &AsF[s * AS_WORDS];
        const float* Bc = &BsF[s * BS_WORDS];
#pragma unroll
        for (int ks = 0; ks < 4; ks++) {
            int kk = ks * 8;
            uint32_t a[2][4];
#pragma unroll
            for (int mt = 0; mt < 2; mt++) {
                int r0 = rbase + mt * 16 + g;
                int c0 = kk + t, c1 = kk + t + 4;
                int p0 = ((c0 >> 2) ^ ((r0 >> 2) & 1)) * 4 + (c0 & 3);
                int p0b = ((c0 >> 2) ^ (((r0 + 8) >> 2) & 1)) * 4 + (c0 & 3);
                int p1 = ((c1 >> 2) ^ ((r0 >> 2) & 1)) * 4 + (c1 & 3);
                int p1b = ((c1 >> 2) ^ (((r0 + 8) >> 2) & 1)) * 4 + (c1 & 3);
                a[mt][0] = to_tf32(Ac[r0 * AS_STRIDE + p0]);
                a[mt][1] = to_tf32(Ac[(r0 + 8) * AS_STRIDE + p0b]);
                a[mt][2] = to_tf32(Ac[r0 * AS_STRIDE + p1]);
                a[mt][3] = to_tf32(Ac[(r0 + 8) * AS_STRIDE + p1b]);
            }
            uint32_t b[4][2];
#pragma unroll
            for (int nt = 0; nt < 4; nt++) {
                int n = cbase + nt * 8 + g;
                b[nt][0] = to_tf32(Bc[(kk + t) * BS_STRIDE + n]);
                b[nt][1] = to_tf32(Bc[(kk + t + 4) * BS_STRIDE + n]);
            }
#pragma unroll
            for (int mt = 0; mt < 2; mt++)
#pragma unroll
                for (int nt = 0; nt < 4; nt++)
                    mma_tf32(acc[mt][nt], a[mt], b[nt]);
        }
        __syncthreads();
        s ^= 1;
    }

    int hA = warp_n * 2, hB = hA + 1;
    float2 alA[2], arA[2], alB[2], arB[2];
#pragma unroll
    for (int q = 0; q < 2; q++) {
        alA[q] = *(const float2*)&attn_l[hA * 16 + q * 8 + t * 2];
        arA[q] = *(const float2*)&attn_r[hA * 16 + q * 8 + t * 2];
        alB[q] = *(const float2*)&attn_l[hB * 16 + q * 8 + t * 2];
        arB[q] = *(const float2*)&attn_r[hB * 16 + q * 8 + t * 2];
    }
    __half2* gfeat2 = (__half2*)g_feat;
#pragma unroll
    for (int mt = 0; mt < 2; mt++)
#pragma unroll
    for (int rr = 0; rr < 2; rr++) {
        int r = rb + rbase + mt * 16 + g + rr * 8;
        float v[4][2];
#pragma unroll
        for (int nt = 0; nt < 4; nt++) {
            v[nt][0] = acc[mt][nt][rr * 2];
            v[nt][1] = acc[mt][nt][rr * 2 + 1];
        }
        if (r < N_NODES) {
#pragma unroll
            for (int nt = 0; nt < 4; nt++)
                gfeat2[(long)r * 32 + (cbase + nt * 8 + t * 2) / 2] =
                    __floats2half2_rn(v[nt][0], v[nt][1]);
        }
        float elA = v[0][0] * alA[0].x + v[0][1] * alA[0].y + v[1][0] * alA[1].x + v[1][1] * alA[1].y;
        float erA = v[0][0] * arA[0].x + v[0][1] * arA[0].y + v[1][0] * arA[1].x + v[1][1] * arA[1].y;
        float elB = v[2][0] * alB[0].x + v[2][1] * alB[0].y + v[3][0] * alB[1].x + v[3][1] * alB[1].y;
        float erB = v[2][0] * arB[0].x + v[2][1] * arB[0].y + v[3][0] * arB[1].x + v[3][1] * arB[1].y;
#pragma unroll
        for (int o = 1; o <= 2; o <<= 1) {
            elA += __shfl_xor_sync(0xffffffffu, elA, o);
            erA += __shfl_xor_sync(0xffffffffu, erA, o);
            elB += __shfl_xor_sync(0xffffffffu, elB, o);
            erB += __shfl_xor_sync(0xffffffffu, erB, o);
        }
        if (t == 0 && r < N_NODES) {
            ((float*)g_el)[r * 4 + hA] = elA;
            ((float*)g_el)[r * 4 + hB] = elB;
            ((float*)g_er)[r * 4 + hA] = erA;
            ((float*)g_er)[r * 4 + hB] = erB;
        }
    }
}

// ---------------- counting sort: scan + scatter -------------------------------
__global__ __launch_bounds__(SCAN_B) void k_scan1() {
    __shared__ int sh[SCAN_B];
    int b = blockIdx.x, t = threadIdx.x;
    int i = b * SCAN_B + t;
    sh[t] = (i < N_NODES) ? g_cnt[i] : 0;
#pragma unroll
    for (int o = 1; o < SCAN_B; o <<= 1) {
        __syncthreads();
        int add = (t >= o) ? sh[t - o] : 0;
        __syncthreads();
        sh[t] += add;
    }
    __syncthreads();
    if (i < N_NODES) g_incl[i] = sh[t];
    if (t == SCAN_B - 1) g_bsum[b] = sh[t];
}

__global__ void k_scan2() {
    __shared__ int sh[128];
    int t = threadIdx.x;
    int v = (t < NB) ? g_bsum[t] : 0;
    sh[t] = v;
#pragma unroll
    for (int o = 1; o < 128; o <<= 1) {
        __syncthreads();
        int add = (t >= o) ? sh[t - o] : 0;
        __syncthreads();
        sh[t] += add;
    }
    __syncthreads();
    if (t < NB) g_boff[t] = sh[t] - v;
}

__global__ void k_scan3() {
    int i = blockIdx.x * 256 + threadIdx.x;
    if (i < N_NODES) {
        int s = g_boff[i >> 10] + g_incl[i] - g_cnt[i];
        g_rowptr[i] = s;
        g_cur[i] = s;
    }
    if (i == 0) g_rowptr[N_NODES] = N_EDGES;
}

__global__ __launch_bounds__(256) void k_scatter(const int* __restrict__ src,
                                                 const int* __restrict__ dst,
                                                 const int* __restrict__ et) {
    int i = blockIdx.x * 256 + threadIdx.x;
    if (i >= N_EDGES) return;
    int p = atomicAdd(&g_cur[dst[i]], 1);
    g_es[p] = make_int2(src[i], (i << 2) | et[i]);
}

// ---------------- fused softmax + aggregate: one warp per dst node -----------
// Two 16-lane halves, each one in-flight edge; fp16 feat row = 128B = 1 line.
__global__ __launch_bounds__(256) void k_agg(float* __restrict__ rst,
                                             float* __restrict__ out_a) {
    int d = (blockIdx.x * 256 + threadIdx.x) >> 5;
    int lane = threadIdx.x & 31;
    if (d >= N_NODES) return;
    int start = g_rowptr[d], end = g_rowptr[d + 1];
    float4* rout4 = (float4*)(rst + (long)d * HD);
    int sl = lane & 15, half = lane >> 4;
    if (start == end) {
        if (half == 0) rout4[sl] = make_float4(0.f, 0.f, 0.f, 0.f);
        return;
    }

    const float* elf = (const float*)g_el;
    const float* erf = (const float*)g_er;
    const float* eef = (const float*)g_ee;
    const uint2* feath = (const uint2*)g_feat;   // 16 x uint2 (4 halves) per node

    int h = sl >> 2;                              // head of cols sl*4..sl*4+3
    float erh = erf[d * 4 + h];
    float ee0 = eef[h], ee1 = eef[4 + h], ee2 = eef[8 + h];

    float z = 0.f;
    float4 acc = make_float4(0.f, 0.f, 0.f, 0.f);
    int e = start + half;
    int2 m = (e < end) ? g_es[e] : make_int2(0, 0);
    for (; e < end; e += 2) {
        int2 mn = m;
        if (e + 2 < end) mn = g_es[e + 2];
        int t = m.y & 3;
        float eet = (t == 0) ? ee0 : ((t == 1) ? ee1 : ee2);
        float sc = elf[m.x * 4 + h] + erh + eet;
        sc = sc > 0.f ? sc : NEG_SLOPE * sc;
        float ev = __expf(sc);
        uint2 fh = feath[(long)m.x * 16 + sl];
        float2 f0 = __half22float2(*(__half2*)&fh.x);
        float2 f1 = __half22float2(*(__half2*)&fh.y);
        z += ev;
        acc.x += f0.x * ev; acc.y += f0.y * ev;
        acc.z += f1.x * ev; acc.w += f1.y * ev;
        m = mn;
    }
    z     += __shfl_xor_sync(0xffffffffu, z, 16);
    acc.x += __shfl_xor_sync(0xffffffffu, acc.x, 16);
    acc.y += __shfl_xor_sync(0xffffffffu, acc.y, 16);
    acc.z += __shfl_xor_sync(0xffffffffu, acc.z, 16);
    acc.w += __shfl_xor_sync(0xffffffffu, acc.w, 16);
    float invz = 1.0f / z;
    if (half == 0)
        rout4[sl] = make_float4(acc.x * invz, acc.y * invz, acc.z * invz, acc.w * invz);

    int h2 = lane & 3, g = lane >> 2;
    float er2 = erf[d * 4 + h2];
    float f0 = eef[h2], f1 = eef[4 + h2], f2 = eef[8 + h2];
    float invz2 = __shfl_sync(0xffffffffu, invz, h2 * 4);
    for (int e0 = start; e0 < end; e0 += 8) {
        int ei = e0 + g;
        if (ei < end) {
            int2 me = g_es[ei];
            int t = me.y & 3;
            float eet = (t == 0) ? f0 : ((t == 1) ? f1 : f2);
            float sc = elf[me.x * 4 + h2] + er2 + eet;
            sc = sc > 0.f ? sc : NEG_SLOPE * sc;
            __stcs(&out_a[(long)(me.y >> 2) * 4 + h2], __expf(sc) * invz2);
        }
    }
}

// ---------------- launch ------------------------------------------------------
extern "C" void kernel_launch(void* const* d_in, const int* in_sizes, int n_in,
                              void* d_out, int out_size) {
    const float* x        = (const float*)d_in[0];
    const float* W        = (const float*)d_in[1];
    const float* W_e      = (const float*)d_in[2];
    const float* attn_l   = (const float*)d_in[3];
    const float* attn_r   = (const float*)d_in[4];
    const float* attn_e   = (const float*)d_in[5];
    const float* edge_emb = (const float*)d_in[6];
    const int*   src      = (const int*)d_in[7];
    const int*   dst      = (const int*)d_in[8];
    const int*   et       = (const int*)d_in[9];

    float* rst   = (float*)d_out;
    float* out_a = rst + (long)N_NODES * HD;

    int nb = (N_NODES + 255) / 256;
    int eb = (N_EDGES + 255) / 256;

    cudaFuncSetAttribute(k_gemm, cudaFuncAttributeMaxDynamicSharedMemorySize, GEMM_SMEM);

    k_init<<<nb, 256>>>();
    k_ee<<<1, 384>>>(W_e, attn_e, edge_emb);
    k_hist<<<eb, 256>>>(dst);
    k_gemm<<<(N_NODES + 127) / 128, 256, GEMM_SMEM>>>(x, W, attn_l, attn_r);   // 4th: profiled
    k_scan1<<<NB, SCAN_B>>>();
    k_scan2<<<1, 128>>>();
    k_scan3<<<nb, 256>>>();
    k_scatter<<<eb, 256>>>(src, dst, et);
    k_agg<<<(N_NODES * 32 + 255) / 256, 256>>>(rst, out_a);
}